// round 14
// baseline (speedup 1.0000x reference)
#include <cuda_runtime.h>
#include <cuda_bf16.h>

// Problem constants
#define BB 8
#define SS 1024
#define DD 768
#define HH 12
#define HD 64
#define NBH (BB * HH)
#define MM (BB * SS)          // 8192 rows

// Scratch (no cudaMalloc allowed)
__device__ __nv_bfloat16 g_qh[NBH * SS * HD];   // (bh, s, d) projected splits
__device__ __nv_bfloat16 g_ql[NBH * SS * HD];
__device__ __nv_bfloat16 g_kh[NBH * SS * HD];
__device__ __nv_bfloat16 g_kl[NBH * SS * HD];
__device__ __nv_bfloat16 g_vh[NBH * SS * HD];
__device__ __nv_bfloat16 g_vl[NBH * SS * HD];
__device__ __nv_bfloat16 g_inh[3L * MM * DD];   // pre-split inputs (q,k,v)
__device__ __nv_bfloat16 g_inl[3L * MM * DD];
__device__ __nv_bfloat16 g_wh[3L * DD * DD];    // pre-split weights
__device__ __nv_bfloat16 g_wl[3L * DD * DD];
__device__ int g_mask_mode;                     // 0=f32, 1=i32, 2=u8

// ---------------------------------------------------------------------------
// Warp-MMA + async helpers (baseline PTX, no 'a'-gated features)
// ---------------------------------------------------------------------------
__device__ __forceinline__ unsigned smem_u32(const void* p) {
    unsigned a;
    asm("{ .reg .u64 t; cvta.to.shared.u64 t, %1; cvt.u32.u64 %0, t; }"
        : "=r"(a) : "l"(p));
    return a;
}
__device__ __forceinline__ void ldsm4(unsigned r[4], unsigned a) {
    asm volatile("ldmatrix.sync.aligned.m8n8.x4.shared.b16 {%0,%1,%2,%3}, [%4];"
                 : "=r"(r[0]), "=r"(r[1]), "=r"(r[2]), "=r"(r[3]) : "r"(a));
}
__device__ __forceinline__ void ldsm4t(unsigned r[4], unsigned a) {
    asm volatile("ldmatrix.sync.aligned.m8n8.x4.trans.shared.b16 {%0,%1,%2,%3}, [%4];"
                 : "=r"(r[0]), "=r"(r[1]), "=r"(r[2]), "=r"(r[3]) : "r"(a));
}
__device__ __forceinline__ void mmabf(float c[4], const unsigned a[4],
                                      unsigned b0, unsigned b1) {
    asm volatile("mma.sync.aligned.m16n8k16.row.col.f32.bf16.bf16.f32 "
                 "{%0,%1,%2,%3}, {%4,%5,%6,%7}, {%8,%9}, {%0,%1,%2,%3};"
                 : "+f"(c[0]), "+f"(c[1]), "+f"(c[2]), "+f"(c[3])
                 : "r"(a[0]), "r"(a[1]), "r"(a[2]), "r"(a[3]), "r"(b0), "r"(b1));
}
__device__ __forceinline__ void cpa16(unsigned saddr, const void* gptr) {
    asm volatile("cp.async.cg.shared.global [%0], [%1], 16;"
                 :: "r"(saddr), "l"(gptr));
}
__device__ __forceinline__ void cpa_commit() {
    asm volatile("cp.async.commit_group;" ::: "memory");
}
__device__ __forceinline__ void cpa_wait1() {
    asm volatile("cp.async.wait_group 1;" ::: "memory");
}
__device__ __forceinline__ void cpa_wait0() {
    asm volatile("cp.async.wait_group 0;" ::: "memory");
}

// split fp32 pair -> two packed-bf16 words (hi pair, lo pair)
__device__ __forceinline__ void split_pair(float a, float b, unsigned& hi, unsigned& lo) {
    __nv_bfloat162 h2 = __floats2bfloat162_rn(a, b);
    float ra = a - __bfloat162float(h2.x);
    float rb = b - __bfloat162float(h2.y);
    __nv_bfloat162 l2 = __floats2bfloat162_rn(ra, rb);
    hi = *(unsigned*)&h2;
    lo = *(unsigned*)&l2;
}

// padded smem row: 72 bf16 (144 B; 144 % 16 == 0 so 16B cp.async stays aligned)
#define PAD 72
#define ROWB 144

// ---------------------------------------------------------------------------
// Pre-split: fp32 array -> bf16 hi/lo arrays. n multiple of 1024.
// ---------------------------------------------------------------------------
__global__ __launch_bounds__(256) void split_kernel(
    const float* __restrict__ src, __nv_bfloat16* __restrict__ dh,
    __nv_bfloat16* __restrict__ dl)
{
    long i = ((long)blockIdx.x * 256 + threadIdx.x) * 4;
    float4 v = *(const float4*)(src + i);
    unsigned h0, l0, h1, l1;
    split_pair(v.x, v.y, h0, l0);
    split_pair(v.z, v.w, h1, l1);
    *(uint2*)(dh + i) = make_uint2(h0, h1);
    *(uint2*)(dl + i) = make_uint2(l0, l1);
}

// ---------------------------------------------------------------------------
// Mask dtype detection
// ---------------------------------------------------------------------------
__global__ void detect_mask_kernel(const unsigned char* __restrict__ m) {
    __shared__ int f32flag, nz123;
    if (threadIdx.x == 0) { f32flag = 0; nz123 = 0; }
    __syncthreads();
    for (int i = threadIdx.x; i < 65536; i += blockDim.x) {
        unsigned char v = m[i];
        if (v) {
            int r = i & 3;
            if ((r == 3 && v == 0x3F) || (r == 2 && v == 0x80)) atomicOr(&f32flag, 1);
            if (r != 0) atomicOr(&nz123, 1);
        }
    }
    __syncthreads();
    if (threadIdx.x == 0)
        g_mask_mode = f32flag ? 0 : (nz123 ? 2 : 1);
}

__device__ __forceinline__ float maskAt(const void* m, long i, int mode) {
    if (mode == 0) return ((const float*)m)[i];
    if (mode == 1) return (float)((const int*)m)[i];
    return (float)((const unsigned char*)m)[i];
}

// ---------------------------------------------------------------------------
// Projection (HMMA + cp.async double buffer): Y = X @ W^T + bias.
// Merged q/k/v: which = blockIdx.z. Tile 128m x 128n (two heads per block).
// 2-stage pipeline: stage c+1 streams under MMA of chunk c. 1 block/SM.
// smem: bias(512) + 2 stages x (AH|AL|BH|BL each 128x144B) = 147968 B.
// ---------------------------------------------------------------------------
#define PJ_TILE 18432                       // 128 * ROWB
#define PJ_STG (4 * PJ_TILE)                // one stage: AH AL BH BL
#define PJ_AH 0
#define PJ_AL PJ_TILE
#define PJ_BH (2 * PJ_TILE)
#define PJ_BL (3 * PJ_TILE)
#define PJ_BASE 512
#define PJ_SMEM (PJ_BASE + 2 * PJ_STG)

__global__ __launch_bounds__(256, 1) void proj_kernel(
    const float* __restrict__ bq, const float* __restrict__ bk,
    const float* __restrict__ bv)
{
    extern __shared__ char dynsm[];
    const unsigned sbase = smem_u32(dynsm);
    const int tid = threadIdx.x;
    const int lane = tid & 31, warp = tid >> 5;
    const int wm = warp & 3, wn = warp >> 2;     // 4m x 2n (64 cols per n-warp)
    const int which = blockIdx.z;
    const int hp = blockIdx.x;                   // head pair
    const int m0 = blockIdx.y * 128;
    const int n0 = hp * 128;

    const __nv_bfloat16* Xh = g_inh + (long)which * MM * DD;
    const __nv_bfloat16* Xl = g_inl + (long)which * MM * DD;
    const __nv_bfloat16* Wh = g_wh + (long)which * DD * DD;
    const __nv_bfloat16* Wl = g_wl + (long)which * DD * DD;
    const float* bias = (which == 0) ? bq : (which == 1) ? bk : bv;

    float* biasSm = (float*)dynsm;
    if (tid < 128) biasSm[tid] = bias[n0 + tid];

    // per-thread staging geometry: row = tid>>1, k-half = (tid&1)*32
    const int srow = tid >> 1, skh = (tid & 1) * 32;
    const long xg = (long)(m0 + srow) * DD + skh;
    const long wg = (long)(n0 + srow) * DD + skh;
    const unsigned soff = (srow * PAD + skh) * 2;

    // issue one chunk's staging into stage buffer sb
    auto issue = [&](int c, int sb) {
        unsigned base = sbase + PJ_BASE + sb * PJ_STG + soff;
        const char* pxh = (const char*)(Xh + xg + c * 64);
        const char* pxl = (const char*)(Xl + xg + c * 64);
        const char* pwh = (const char*)(Wh + wg + c * 64);
        const char* pwl = (const char*)(Wl + wg + c * 64);
#pragma unroll
        for (int i = 0; i < 4; i++) {
            cpa16(base + PJ_AH + i * 16, pxh + i * 16);
            cpa16(base + PJ_AL + i * 16, pxl + i * 16);
            cpa16(base + PJ_BH + i * 16, pwh + i * 16);
            cpa16(base + PJ_BL + i * 16, pwl + i * 16);
        }
        cpa_commit();
    };

    float acc[2][8][4];
#pragma unroll
    for (int i = 0; i < 2; i++)
#pragma unroll
        for (int j = 0; j < 8; j++)
#pragma unroll
            for (int u = 0; u < 4; u++) acc[i][j][u] = 0.f;

    const int o8 = lane >> 3;
    const unsigned a_off = ((wm * 32 + (lane & 15)) * PAD + (lane >> 4) * 8) * 2;
    const unsigned b_off = ((wn * 64 + (lane & 7) + (o8 >> 1) * 8) * PAD + (o8 & 1) * 8) * 2;

    issue(0, 0);            // prologue

    for (int c = 0; c < 12; c++) {
        const int buf = c & 1;
        if (c + 1 < 12) { issue(c + 1, buf ^ 1); cpa_wait1(); }
        else            cpa_wait0();
        __syncthreads();

        const unsigned sb = sbase + PJ_BASE + buf * PJ_STG;
#pragma unroll
        for (int kk = 0; kk < 64; kk += 16) {
            unsigned Ah[2][4], Al[2][4], B[4][4];
            ldsm4(Ah[0], sb + PJ_AH + a_off + kk * 2);
            ldsm4(Ah[1], sb + PJ_AH + a_off + kk * 2 + 16 * ROWB);
            ldsm4(Al[0], sb + PJ_AL + a_off + kk * 2);
            ldsm4(Al[1], sb + PJ_AL + a_off + kk * 2 + 16 * ROWB);
#pragma unroll
            for (int j = 0; j < 4; j++)
                ldsm4(B[j], sb + PJ_BH + b_off + kk * 2 + j * 16 * ROWB);
#pragma unroll
            for (int mi = 0; mi < 2; mi++)
#pragma unroll
                for (int j = 0; j < 4; j++) {
                    mmabf(acc[mi][2 * j], Ah[mi], B[j][0], B[j][1]);
                    mmabf(acc[mi][2 * j + 1], Ah[mi], B[j][2], B[j][3]);
                }
#pragma unroll
            for (int mi = 0; mi < 2; mi++)
#pragma unroll
                for (int j = 0; j < 4; j++) {
                    mmabf(acc[mi][2 * j], Al[mi], B[j][0], B[j][1]);
                    mmabf(acc[mi][2 * j + 1], Al[mi], B[j][2], B[j][3]);
                }
#pragma unroll
            for (int j = 0; j < 4; j++)
                ldsm4(B[j], sb + PJ_BL + b_off + kk * 2 + j * 16 * ROWB);
#pragma unroll
            for (int mi = 0; mi < 2; mi++)
#pragma unroll
                for (int j = 0; j < 4; j++) {
                    mmabf(acc[mi][2 * j], Ah[mi], B[j][0], B[j][1]);
                    mmabf(acc[mi][2 * j + 1], Ah[mi], B[j][2], B[j][3]);
                }
        }
        __syncthreads();   // all reads of buf done before it is re-staged
    }

    __nv_bfloat16* dh = (which == 0) ? g_qh : (which == 1) ? g_kh : g_vh;
    __nv_bfloat16* dl = (which == 0) ? g_ql : (which == 1) ? g_kl : g_vl;
    const int r0 = lane >> 2, cp = (lane & 3) * 2;
#pragma unroll
    for (int mi = 0; mi < 2; mi++)
#pragma unroll
        for (int j = 0; j < 8; j++) {
            int cg = wn * 64 + j * 8 + cp;        // 0..127 within head pair
            int h = hp * 2 + (cg >> 6);
            int d = cg & 63;
            float b0v = biasSm[cg], b1v = biasSm[cg + 1];
#pragma unroll
            for (int half = 0; half < 2; half++) {
                int m = m0 + wm * 32 + mi * 16 + r0 + half * 8;
                int b = m >> 10, s = m & 1023;
                long bh = (long)(b * HH + h);
                float y0 = acc[mi][j][half * 2] + b0v;
                float y1 = acc[mi][j][half * 2 + 1] + b1v;
                unsigned hv, lv;
                split_pair(y0, y1, hv, lv);
                long base = (bh * SS + s) * HD + d;
                *(unsigned*)(dh + base) = hv;
                *(unsigned*)(dl + base) = lv;
            }
        }
}

// ---------------------------------------------------------------------------
// Scores (HMMA): S = (Q K^T)/8 -> prob region (fp32 scratch).  [R10 proven]
// ---------------------------------------------------------------------------
#define SC_QH 0
#define SC_QL (SC_QH + 128 * ROWB)
#define SC_KH (SC_QL + 128 * ROWB)
#define SC_KL (SC_KH + 128 * ROWB)
#define SC_SMEM (SC_KL + 128 * ROWB)

__global__ __launch_bounds__(256, 2) void score_kernel(float* __restrict__ prob)
{
    extern __shared__ char dynsm[];
    const unsigned sbase = smem_u32(dynsm);
    const int tid = threadIdx.x;
    const int lane = tid & 31, warp = tid >> 5;
    const int wm = warp & 3, wn = warp >> 2;
    const int bh = blockIdx.z;
    const int q0 = blockIdx.y * 128, k0 = blockIdx.x * 128;

    {   // stage 4 bf16 tiles: 128 rows x 64 d each
        int row = tid >> 1, hd0 = (tid & 1) * 32;
        long qrow = ((long)bh * SS + q0 + row) * HD + hd0;
        long krow = ((long)bh * SS + k0 + row) * HD + hd0;
        unsigned so = (row * PAD + hd0) * 2;
#pragma unroll
        for (int i = 0; i < 4; i++) {
            *(float4*)(dynsm + SC_QH + so + i * 16) = *(const float4*)(g_qh + qrow + i * 8);
            *(float4*)(dynsm + SC_QL + so + i * 16) = *(const float4*)(g_ql + qrow + i * 8);
            *(float4*)(dynsm + SC_KH + so + i * 16) = *(const float4*)(g_kh + krow + i * 8);
            *(float4*)(dynsm + SC_KL + so + i * 16) = *(const float4*)(g_kl + krow + i * 8);
        }
    }
    __syncthreads();

    float acc[2][8][4];
#pragma unroll
    for (int i = 0; i < 2; i++)
#pragma unroll
        for (int j = 0; j < 8; j++)
#pragma unroll
            for (int u = 0; u < 4; u++) acc[i][j][u] = 0.f;

    const int o8 = lane >> 3;
    const unsigned a_off = ((wm * 32 + (lane & 15)) * PAD + (lane >> 4) * 8) * 2;
    const unsigned b_off = ((wn * 64 + (lane & 7) + (o8 >> 1) * 8) * PAD + (o8 & 1) * 8) * 2;

#pragma unroll
    for (int kk = 0; kk < 64; kk += 16) {
        unsigned Ah[2][4], Al[2][4], B[4][4];
        ldsm4(Ah[0], sbase + SC_QH + a_off + kk * 2);
        ldsm4(Ah[1], sbase + SC_QH + a_off + kk * 2 + 16 * ROWB);
        ldsm4(Al[0], sbase + SC_QL + a_off + kk * 2);
        ldsm4(Al[1], sbase + SC_QL + a_off + kk * 2 + 16 * ROWB);
#pragma unroll
        for (int j = 0; j < 4; j++)
            ldsm4(B[j], sbase + SC_KH + b_off + kk * 2 + j * 16 * ROWB);
#pragma unroll
        for (int mi = 0; mi < 2; mi++)
#pragma unroll
            for (int j = 0; j < 4; j++) {
                mmabf(acc[mi][2 * j], Ah[mi], B[j][0], B[j][1]);
                mmabf(acc[mi][2 * j + 1], Ah[mi], B[j][2], B[j][3]);
            }
#pragma unroll
        for (int mi = 0; mi < 2; mi++)
#pragma unroll
            for (int j = 0; j < 4; j++) {
                mmabf(acc[mi][2 * j], Al[mi], B[j][0], B[j][1]);
                mmabf(acc[mi][2 * j + 1], Al[mi], B[j][2], B[j][3]);
            }
#pragma unroll
        for (int j = 0; j < 4; j++)
            ldsm4(B[j], sbase + SC_KL + b_off + kk * 2 + j * 16 * ROWB);
#pragma unroll
        for (int mi = 0; mi < 2; mi++)
#pragma unroll
            for (int j = 0; j < 4; j++) {
                mmabf(acc[mi][2 * j], Ah[mi], B[j][0], B[j][1]);
                mmabf(acc[mi][2 * j + 1], Ah[mi], B[j][2], B[j][3]);
            }
    }

    const int r0 = lane >> 2, cp = (lane & 3) * 2;
#pragma unroll
    for (int mi = 0; mi < 2; mi++)
#pragma unroll
        for (int j = 0; j < 8; j++) {
            int k = k0 + wn * 64 + j * 8 + cp;
#pragma unroll
            for (int half = 0; half < 2; half++) {
                int q = q0 + wm * 32 + mi * 16 + r0 + half * 8;
                float2 o;
                o.x = acc[mi][j][half * 2] * 0.125f;
                o.y = acc[mi][j][half * 2 + 1] * 0.125f;
                *(float2*)(prob + ((long)bh * SS + q) * SS + k) = o;
            }
        }
}

// ---------------------------------------------------------------------------
// Softmax + mask + rel-blend, in place on prob.  [R13 proven]
// 384 threads = 12 warps; phase A rel_attn once, phase B warp-per-head.
// ---------------------------------------------------------------------------
#define SM_WARPS 12

__device__ __forceinline__ float bredMax12(float v, volatile float* red) {
#pragma unroll
    for (int o = 16; o; o >>= 1) v = fmaxf(v, __shfl_xor_sync(0xffffffffu, v, o));
    if ((threadIdx.x & 31) == 0) red[threadIdx.x >> 5] = v;
    __syncthreads();
    float r = red[0];
#pragma unroll
    for (int i = 1; i < SM_WARPS; i++) r = fmaxf(r, red[i]);
    __syncthreads();
    return r;
}
__device__ __forceinline__ float bredSum12(float v, volatile float* red) {
#pragma unroll
    for (int o = 16; o; o >>= 1) v += __shfl_xor_sync(0xffffffffu, v, o);
    if ((threadIdx.x & 31) == 0) red[threadIdx.x >> 5] = v;
    __syncthreads();
    float r = 0.f;
#pragma unroll
    for (int i = 0; i < SM_WARPS; i++) r += red[i];
    __syncthreads();
    return r;
}

__global__ __launch_bounds__(384) void softmax_kernel(
    const float* __restrict__ rel, const void* __restrict__ mask,
    const float* __restrict__ l1p, float* __restrict__ prob)
{
    __shared__ float relp[1024];   // l1 * rel_attn
    __shared__ float msk[1024];
    __shared__ float red[SM_WARPS];

    const int b = blockIdx.y, q = blockIdx.x, tid = threadIdx.x;
    const int mode = g_mask_mode;
    const long mbase = ((long)(b * SS + q)) * SS;

    // ---- Phase A: rel_attn row (head-independent), once ----
    float v[4] = {-3.0e38f, -3.0e38f, -3.0e38f, -3.0e38f};
    float rr[4];
    if (tid < 256) {
        float4 r4 = *(const float4*)(rel + mbase + tid * 4);
        rr[0] = r4.x; rr[1] = r4.y; rr[2] = r4.z; rr[3] = r4.w;
#pragma unroll
        for (int u = 0; u < 4; u++) {
            float mv = maskAt(mask, mbase + tid * 4 + u, mode);
            msk[tid * 4 + u] = mv;
            v[u] = (mv != 0.f) ? rr[u] : -1.0e4f;
        }
    }
    float mx = bredMax12(fmaxf(fmaxf(v[0], v[1]), fmaxf(v[2], v[3])), red);
    float e[4] = {0.f, 0.f, 0.f, 0.f};
    float s = 0.f;
    if (tid < 256) {
#pragma unroll
        for (int u = 0; u < 4; u++) { e[u] = __expf(v[u] - mx); s += e[u]; }
    }
    float tot = bredSum12(s, red);
    const float l1v = *l1p;
    const float w0 = 1.f - l1v;
    float li = l1v / tot;
    if (tid < 256) {
#pragma unroll
        for (int u = 0; u < 4; u++) relp[tid * 4 + u] = e[u] * li;
    }
    __syncthreads();

    // ---- Phase B: one warp per head ----
    const int warp = tid >> 5, lane = tid & 31;
    const int h = warp;
    float* row = prob + (((long)(b * HH + h) * SS) + q) * SS;
    float sv[32];
    float hm = -3.0e38f;
#pragma unroll
    for (int i = 0; i < 8; i++) {
        int idx = i * 128 + lane * 4;
        float4 s4 = *(const float4*)(row + idx);
        float t0 = (msk[idx + 0] != 0.f) ? -1.0e9f : s4.x;
        float t1 = (msk[idx + 1] != 0.f) ? -1.0e9f : s4.y;
        float t2 = (msk[idx + 2] != 0.f) ? -1.0e9f : s4.z;
        float t3 = (msk[idx + 3] != 0.f) ? -1.0e9f : s4.w;
        sv[i * 4 + 0] = t0; sv[i * 4 + 1] = t1;
        sv[i * 4 + 2] = t2; sv[i * 4 + 3] = t3;
        hm = fmaxf(hm, fmaxf(fmaxf(t0, t1), fmaxf(t2, t3)));
    }
#pragma unroll
    for (int o = 16; o; o >>= 1) hm = fmaxf(hm, __shfl_xor_sync(0xffffffffu, hm, o));
    float hs = 0.f;
#pragma unroll
    for (int i = 0; i < 32; i++) {
        sv[i] = __expf(sv[i] - hm);
        hs += sv[i];
    }
#pragma unroll
    for (int o = 16; o; o >>= 1) hs += __shfl_xor_sync(0xffffffffu, hs, o);
    float wi = w0 / hs;
#pragma unroll
    for (int i = 0; i < 8; i++) {
        int idx = i * 128 + lane * 4;
        float4 o4;
        o4.x = sv[i * 4 + 0] * wi + relp[idx + 0];
        o4.y = sv[i * 4 + 1] * wi + relp[idx + 1];
        o4.z = sv[i * 4 + 2] * wi + relp[idx + 2];
        o4.w = sv[i * 4 + 3] * wi + relp[idx + 3];
        *(float4*)(row + idx) = o4;
    }
}

// ---------------------------------------------------------------------------
// PV (HMMA): out[bh,q,d] = sum_s P[q][s] * V[s][d].  [R10 proven]
// ---------------------------------------------------------------------------
#define PV_PH 0
#define PV_PL (PV_PH + 128 * ROWB)
#define PV_VH (PV_PL + 128 * ROWB)
#define PV_VL (PV_VH + 64 * ROWB)
#define PV_SMEM (PV_VL + 64 * ROWB)

__global__ __launch_bounds__(256, 2) void pv_kernel(
    const float* __restrict__ prob, float* __restrict__ out0)
{
    extern __shared__ char dynsm[];
    const unsigned sbase = smem_u32(dynsm);
    const int tid = threadIdx.x;
    const int lane = tid & 31, warp = tid >> 5;
    const int wm = warp & 3, wn = warp >> 2;
    const int bh = blockIdx.y;
    const int q0 = blockIdx.x * 128;
    const int b = bh / HH, h = bh - b * HH;

    float acc[2][4][4];
#pragma unroll
    for (int i = 0; i < 2; i++)
#pragma unroll
        for (int j = 0; j < 4; j++)
#pragma unroll
            for (int u = 0; u < 4; u++) acc[i][j][u] = 0.f;

    const int o8 = lane >> 3;
    const unsigned a_off = ((wm * 32 + (lane & 15)) * PAD + (lane >> 4) * 8) * 2;
    const unsigned bt_row = (lane & 7) + (o8 & 1) * 8;
    const unsigned bt_col = wn * 32 + (o8 >> 1) * 8;

    for (int c = 0; c < 16; c++) {
        __syncthreads();
        {   // stage P chunk: 128 q-rows x 64 s fp32 -> split
            int row = tid >> 1, sh = (tid & 1) * 32;
            const float* g = prob + ((long)bh * SS + q0 + row) * SS + c * 64 + sh;
#pragma unroll
            for (int i = 0; i < 8; i++) {
                float4 v = *(const float4*)(g + i * 4);
                unsigned h0, l0, h1, l1;
                split_pair(v.x, v.y, h0, l0);
                split_pair(v.z, v.w, h1, l1);
                unsigned o = (row * PAD + sh + i * 4) * 2;
                *(uint2*)(dynsm + PV_PH + o) = make_uint2(h0, h1);
                *(uint2*)(dynsm + PV_PL + o) = make_uint2(l0, l1);
            }
        }
        {   // stage V chunk: 64 s-rows x 64 d bf16 (hi/lo)
            int s = tid >> 2, dq = (tid & 3) * 16;
            long idx = ((long)bh * SS + c * 64 + s) * HD + dq;
            unsigned so = (s * PAD + dq) * 2;
            *(float4*)(dynsm + PV_VH + so) = *(const float4*)(g_vh + idx);
            *(float4*)(dynsm + PV_VH + so + 16) = *(const float4*)(g_vh + idx + 8);
            *(float4*)(dynsm + PV_VL + so) = *(const float4*)(g_vl + idx);
            *(float4*)(dynsm + PV_VL + so + 16) = *(const float4*)(g_vl + idx + 8);
        }
        __syncthreads();

#pragma unroll
        for (int kk = 0; kk < 64; kk += 16) {
            unsigned Ah[2][4], Al[2][4], B[2][4];
            ldsm4(Ah[0], sbase + PV_PH + a_off + kk * 2);
            ldsm4(Ah[1], sbase + PV_PH + a_off + kk * 2 + 16 * ROWB);
            ldsm4(Al[0], sbase + PV_PL + a_off + kk * 2);
            ldsm4(Al[1], sbase + PV_PL + a_off + kk * 2 + 16 * ROWB);
            unsigned bo = ((kk + bt_row) * PAD + bt_col) * 2;
            ldsm4t(B[0], sbase + PV_VH + bo);
            ldsm4t(B[1], sbase + PV_VH + bo + 16 * 2);
#pragma unroll
            for (int mi = 0; mi < 2; mi++)
#pragma unroll
                for (int j = 0; j < 2; j++) {
                    mmabf(acc[mi][2 * j], Ah[mi], B[j][0], B[j][1]);
                    mmabf(acc[mi][2 * j + 1], Ah[mi], B[j][2], B[j][3]);
                }
#pragma unroll
            for (int mi = 0; mi < 2; mi++)
#pragma unroll
                for (int j = 0; j < 2; j++) {
                    mmabf(acc[mi][2 * j], Al[mi], B[j][0], B[j][1]);
                    mmabf(acc[mi][2 * j + 1], Al[mi], B[j][2], B[j][3]);
                }
            ldsm4t(B[0], sbase + PV_VL + bo);
            ldsm4t(B[1], sbase + PV_VL + bo + 16 * 2);
#pragma unroll
            for (int mi = 0; mi < 2; mi++)
#pragma unroll
                for (int j = 0; j < 2; j++) {
                    mmabf(acc[mi][2 * j], Ah[mi], B[j][0], B[j][1]);
                    mmabf(acc[mi][2 * j + 1], Ah[mi], B[j][2], B[j][3]);
                }
        }
    }

    const int r0 = lane >> 2, cp = (lane & 3) * 2;
#pragma unroll
    for (int mi = 0; mi < 2; mi++)
#pragma unroll
        for (int j2 = 0; j2 < 4; j2++) {
            int d = wn * 32 + j2 * 8 + cp;
#pragma unroll
            for (int half = 0; half < 2; half++) {
                int q = q0 + wm * 32 + mi * 16 + r0 + half * 8;
                float2 o;
                o.x = acc[mi][j2][half * 2];
                o.y = acc[mi][j2][half * 2 + 1];
                *(float2*)(out0 + ((long)(b * SS) + q) * DD + h * HD + d) = o;
            }
        }
}

// ---------------------------------------------------------------------------
extern "C" void kernel_launch(void* const* d_in, const int* in_sizes, int n_in,
                              void* d_out, int out_size)
{
    const float* query = (const float*)d_in[0];
    const float* key_t = (const float*)d_in[1];
    const float* value = (const float*)d_in[2];
    const float* rel   = (const float*)d_in[3];
    const void*  mask  = d_in[4];
    const float* l1    = (const float*)d_in[5];
    const float* Wq = (const float*)d_in[6];
    const float* bq = (const float*)d_in[7];
    const float* Wk = (const float*)d_in[8];
    const float* bk = (const float*)d_in[9];
    const float* Wv = (const float*)d_in[10];
    const float* bv = (const float*)d_in[11];

    float* out0 = (float*)d_out;                 // (B,S,D)
    float* prob = out0 + (long)BB * SS * DD;     // (B,H,S,S) scores->prob

    cudaFuncSetAttribute(proj_kernel,
                         cudaFuncAttributeMaxDynamicSharedMemorySize, PJ_SMEM);
    cudaFuncSetAttribute(score_kernel,
                         cudaFuncAttributeMaxDynamicSharedMemorySize, SC_SMEM);
    cudaFuncSetAttribute(pv_kernel,
                         cudaFuncAttributeMaxDynamicSharedMemorySize, PV_SMEM);

    detect_mask_kernel<<<1, 256>>>((const unsigned char*)mask);

    // Pre-split inputs and weights into bf16 hi/lo
    __nv_bfloat16 *inh, *inl, *wh, *wl;
    cudaGetSymbolAddress((void**)&inh, g_inh);
    cudaGetSymbolAddress((void**)&inl, g_inl);
    cudaGetSymbolAddress((void**)&wh, g_wh);
    cudaGetSymbolAddress((void**)&wl, g_wl);
    const long XN = (long)MM * DD, WN = (long)DD * DD;
    split_kernel<<<XN / 1024, 256>>>(query, inh, inl);
    split_kernel<<<XN / 1024, 256>>>(key_t, inh + XN, inl + XN);
    split_kernel<<<XN / 1024, 256>>>(value, inh + 2 * XN, inl + 2 * XN);
    split_kernel<<<WN / 1024, 256>>>(Wq, wh, wl);
    split_kernel<<<WN / 1024, 256>>>(Wk, wh + WN, wl + WN);
    split_kernel<<<WN / 1024, 256>>>(Wv, wh + 2 * WN, wl + 2 * WN);

    dim3 pgrid(DD / 128, MM / 128, 3);
    proj_kernel<<<pgrid, 256, PJ_SMEM>>>(bq, bk, bv);

    dim3 sgrid(SS / 128, SS / 128, NBH);
    score_kernel<<<sgrid, 256, SC_SMEM>>>(prob);

    dim3 smgrid(SS, BB);
    softmax_kernel<<<smgrid, 384>>>(rel, mask, l1, prob);

    dim3 vgrid(SS / 128, NBH);
    pv_kernel<<<vgrid, 256, PV_SMEM>>>(prob, out0);
}

// round 16
// speedup vs baseline: 1.1021x; 1.1021x over previous
#include <cuda_runtime.h>
#include <cuda_bf16.h>

// Problem constants
#define BB 8
#define SS 1024
#define DD 768
#define HH 12
#define HD 64
#define NBH (BB * HH)
#define MM (BB * SS)          // 8192 rows

// Scratch (no cudaMalloc allowed)
__device__ __nv_bfloat16 g_qh[NBH * SS * HD];   // (bh, s, d) projected splits
__device__ __nv_bfloat16 g_ql[NBH * SS * HD];
__device__ __nv_bfloat16 g_kh[NBH * SS * HD];
__device__ __nv_bfloat16 g_kl[NBH * SS * HD];
__device__ __nv_bfloat16 g_vh[NBH * SS * HD];
__device__ __nv_bfloat16 g_vl[NBH * SS * HD];
__device__ __nv_bfloat16 g_inh[3L * MM * DD];   // pre-split inputs (q,k,v)
__device__ __nv_bfloat16 g_inl[3L * MM * DD];
__device__ __nv_bfloat16 g_wh[3L * DD * DD];    // pre-split weights
__device__ __nv_bfloat16 g_wl[3L * DD * DD];
__device__ int g_mask_mode;                     // 0=f32, 1=i32, 2=u8

// ---------------------------------------------------------------------------
// Warp-MMA helpers (baseline PTX, no 'a'-gated features)
// ---------------------------------------------------------------------------
__device__ __forceinline__ unsigned smem_u32(const void* p) {
    unsigned a;
    asm("{ .reg .u64 t; cvta.to.shared.u64 t, %1; cvt.u32.u64 %0, t; }"
        : "=r"(a) : "l"(p));
    return a;
}
__device__ __forceinline__ void ldsm4(unsigned r[4], unsigned a) {
    asm volatile("ldmatrix.sync.aligned.m8n8.x4.shared.b16 {%0,%1,%2,%3}, [%4];"
                 : "=r"(r[0]), "=r"(r[1]), "=r"(r[2]), "=r"(r[3]) : "r"(a));
}
__device__ __forceinline__ void ldsm4t(unsigned r[4], unsigned a) {
    asm volatile("ldmatrix.sync.aligned.m8n8.x4.trans.shared.b16 {%0,%1,%2,%3}, [%4];"
                 : "=r"(r[0]), "=r"(r[1]), "=r"(r[2]), "=r"(r[3]) : "r"(a));
}
__device__ __forceinline__ void mmabf(float c[4], const unsigned a[4],
                                      unsigned b0, unsigned b1) {
    asm volatile("mma.sync.aligned.m16n8k16.row.col.f32.bf16.bf16.f32 "
                 "{%0,%1,%2,%3}, {%4,%5,%6,%7}, {%8,%9}, {%0,%1,%2,%3};"
                 : "+f"(c[0]), "+f"(c[1]), "+f"(c[2]), "+f"(c[3])
                 : "r"(a[0]), "r"(a[1]), "r"(a[2]), "r"(a[3]), "r"(b0), "r"(b1));
}

// split fp32 pair -> two packed-bf16 words (hi pair, lo pair)
__device__ __forceinline__ void split_pair(float a, float b, unsigned& hi, unsigned& lo) {
    __nv_bfloat162 h2 = __floats2bfloat162_rn(a, b);
    float ra = a - __bfloat162float(h2.x);
    float rb = b - __bfloat162float(h2.y);
    __nv_bfloat162 l2 = __floats2bfloat162_rn(ra, rb);
    hi = *(unsigned*)&h2;
    lo = *(unsigned*)&l2;
}

// padded smem row: 72 bf16 (144 B)
#define PAD 72
#define ROWB 144

// ---------------------------------------------------------------------------
// Pre-split: fp32 array -> bf16 hi/lo arrays. n multiple of 1024.
// ---------------------------------------------------------------------------
__global__ __launch_bounds__(256) void split_kernel(
    const float* __restrict__ src, __nv_bfloat16* __restrict__ dh,
    __nv_bfloat16* __restrict__ dl)
{
    long i = ((long)blockIdx.x * 256 + threadIdx.x) * 4;
    float4 v = *(const float4*)(src + i);
    unsigned h0, l0, h1, l1;
    split_pair(v.x, v.y, h0, l0);
    split_pair(v.z, v.w, h1, l1);
    *(uint2*)(dh + i) = make_uint2(h0, h1);
    *(uint2*)(dl + i) = make_uint2(l0, l1);
}

// ---------------------------------------------------------------------------
// Mask dtype detection
// ---------------------------------------------------------------------------
__global__ void detect_mask_kernel(const unsigned char* __restrict__ m) {
    __shared__ int f32flag, nz123;
    if (threadIdx.x == 0) { f32flag = 0; nz123 = 0; }
    __syncthreads();
    for (int i = threadIdx.x; i < 65536; i += blockDim.x) {
        unsigned char v = m[i];
        if (v) {
            int r = i & 3;
            if ((r == 3 && v == 0x3F) || (r == 2 && v == 0x80)) atomicOr(&f32flag, 1);
            if (r != 0) atomicOr(&nz123, 1);
        }
    }
    __syncthreads();
    if (threadIdx.x == 0)
        g_mask_mode = f32flag ? 0 : (nz123 ? 2 : 1);
}

__device__ __forceinline__ float maskAt(const void* m, long i, int mode) {
    if (mode == 0) return ((const float*)m)[i];
    if (mode == 1) return (float)((const int*)m)[i];
    return (float)((const unsigned char*)m)[i];
}

// ---------------------------------------------------------------------------
// Projection (HMMA): Y = X @ W^T + bias -> bf16 hi/lo splits [bh][s][d].
// Tile 128m x 128n (two heads per block), which = blockIdx.z (merged launch).
// 2 blocks/SM, single-buffer LDG staging. [R13-proven core + merge only]
// ---------------------------------------------------------------------------
#define PJ_BIAS 0
#define PJ_AH 512
#define PJ_AL (PJ_AH + 128 * ROWB)
#define PJ_BH (PJ_AL + 128 * ROWB)
#define PJ_BL (PJ_BH + 128 * ROWB)
#define PJ_SMEM (PJ_BL + 128 * ROWB)

__global__ __launch_bounds__(256, 2) void proj_kernel(
    const float* __restrict__ bq, const float* __restrict__ bk,
    const float* __restrict__ bv)
{
    extern __shared__ char dynsm[];
    const unsigned sbase = smem_u32(dynsm);
    const int tid = threadIdx.x;
    const int lane = tid & 31, warp = tid >> 5;
    const int wm = warp & 3, wn = warp >> 2;     // 4m x 2n (64 cols per n-warp)
    const int which = blockIdx.z;
    const int hp = blockIdx.x;                   // head pair
    const int m0 = blockIdx.y * 128;
    const int n0 = hp * 128;

    const __nv_bfloat16* Xh = g_inh + (long)which * MM * DD;
    const __nv_bfloat16* Xl = g_inl + (long)which * MM * DD;
    const __nv_bfloat16* Wh = g_wh + (long)which * DD * DD;
    const __nv_bfloat16* Wl = g_wl + (long)which * DD * DD;
    const float* bias = (which == 0) ? bq : (which == 1) ? bk : bv;

    float* biasSm = (float*)(dynsm + PJ_BIAS);
    if (tid < 128) biasSm[tid] = bias[n0 + tid];

    float acc[2][8][4];
#pragma unroll
    for (int i = 0; i < 2; i++)
#pragma unroll
        for (int j = 0; j < 8; j++)
#pragma unroll
            for (int u = 0; u < 4; u++) acc[i][j][u] = 0.f;

    const int o8 = lane >> 3;
    const unsigned a_off = ((wm * 32 + (lane & 15)) * PAD + (lane >> 4) * 8) * 2;
    const unsigned b_off = ((wn * 64 + (lane & 7) + (o8 >> 1) * 8) * PAD + (o8 & 1) * 8) * 2;

    for (int c = 0; c < 12; c++) {
        __syncthreads();
        {   // stage X chunk: 128 rows x 64 k (hi/lo)
            int row = tid >> 1, kh = (tid & 1) * 32;
            long gi = (long)(m0 + row) * DD + c * 64 + kh;
            unsigned o = (row * PAD + kh) * 2;
#pragma unroll
            for (int i = 0; i < 4; i++) {
                *(float4*)(dynsm + PJ_AH + o + i * 16) = *(const float4*)(Xh + gi + i * 8);
                *(float4*)(dynsm + PJ_AL + o + i * 16) = *(const float4*)(Xl + gi + i * 8);
            }
        }
        {   // stage W chunk: 128 rows x 64 k (hi/lo)
            int row = tid >> 1, kh = (tid & 1) * 32;
            long gi = (long)(n0 + row) * DD + c * 64 + kh;
            unsigned o = (row * PAD + kh) * 2;
#pragma unroll
            for (int i = 0; i < 4; i++) {
                *(float4*)(dynsm + PJ_BH + o + i * 16) = *(const float4*)(Wh + gi + i * 8);
                *(float4*)(dynsm + PJ_BL + o + i * 16) = *(const float4*)(Wl + gi + i * 8);
            }
        }
        __syncthreads();

#pragma unroll
        for (int kk = 0; kk < 64; kk += 16) {
            unsigned Ah[2][4], Al[2][4], B[4][4];
            ldsm4(Ah[0], sbase + PJ_AH + a_off + kk * 2);
            ldsm4(Ah[1], sbase + PJ_AH + a_off + kk * 2 + 16 * ROWB);
            ldsm4(Al[0], sbase + PJ_AL + a_off + kk * 2);
            ldsm4(Al[1], sbase + PJ_AL + a_off + kk * 2 + 16 * ROWB);
#pragma unroll
            for (int j = 0; j < 4; j++)
                ldsm4(B[j], sbase + PJ_BH + b_off + kk * 2 + j * 16 * ROWB);
#pragma unroll
            for (int mi = 0; mi < 2; mi++)
#pragma unroll
                for (int j = 0; j < 4; j++) {
                    mmabf(acc[mi][2 * j], Ah[mi], B[j][0], B[j][1]);
                    mmabf(acc[mi][2 * j + 1], Ah[mi], B[j][2], B[j][3]);
                }
#pragma unroll
            for (int mi = 0; mi < 2; mi++)
#pragma unroll
                for (int j = 0; j < 4; j++) {
                    mmabf(acc[mi][2 * j], Al[mi], B[j][0], B[j][1]);
                    mmabf(acc[mi][2 * j + 1], Al[mi], B[j][2], B[j][3]);
                }
#pragma unroll
            for (int j = 0; j < 4; j++)
                ldsm4(B[j], sbase + PJ_BL + b_off + kk * 2 + j * 16 * ROWB);
#pragma unroll
            for (int mi = 0; mi < 2; mi++)
#pragma unroll
                for (int j = 0; j < 4; j++) {
                    mmabf(acc[mi][2 * j], Ah[mi], B[j][0], B[j][1]);
                    mmabf(acc[mi][2 * j + 1], Ah[mi], B[j][2], B[j][3]);
                }
        }
    }

    __nv_bfloat16* dh = (which == 0) ? g_qh : (which == 1) ? g_kh : g_vh;
    __nv_bfloat16* dl = (which == 0) ? g_ql : (which == 1) ? g_kl : g_vl;
    const int r0 = lane >> 2, cp = (lane & 3) * 2;
#pragma unroll
    for (int mi = 0; mi < 2; mi++)
#pragma unroll
        for (int j = 0; j < 8; j++) {
            int cg = wn * 64 + j * 8 + cp;        // 0..127 within head pair
            int h = hp * 2 + (cg >> 6);
            int d = cg & 63;
            float b0v = biasSm[cg], b1v = biasSm[cg + 1];
#pragma unroll
            for (int half = 0; half < 2; half++) {
                int m = m0 + wm * 32 + mi * 16 + r0 + half * 8;
                int b = m >> 10, s = m & 1023;
                long bh = (long)(b * HH + h);
                float y0 = acc[mi][j][half * 2] + b0v;
                float y1 = acc[mi][j][half * 2 + 1] + b1v;
                unsigned hv, lv;
                split_pair(y0, y1, hv, lv);
                long base = (bh * SS + s) * HD + d;
                *(unsigned*)(dh + base) = hv;
                *(unsigned*)(dl + base) = lv;
            }
        }
}

// ---------------------------------------------------------------------------
// Scores (HMMA): S = (Q K^T)/8 -> prob region (fp32 scratch).  [R10 proven]
// ---------------------------------------------------------------------------
#define SC_QH 0
#define SC_QL (SC_QH + 128 * ROWB)
#define SC_KH (SC_QL + 128 * ROWB)
#define SC_KL (SC_KH + 128 * ROWB)
#define SC_SMEM (SC_KL + 128 * ROWB)

__global__ __launch_bounds__(256, 2) void score_kernel(float* __restrict__ prob)
{
    extern __shared__ char dynsm[];
    const unsigned sbase = smem_u32(dynsm);
    const int tid = threadIdx.x;
    const int lane = tid & 31, warp = tid >> 5;
    const int wm = warp & 3, wn = warp >> 2;
    const int bh = blockIdx.z;
    const int q0 = blockIdx.y * 128, k0 = blockIdx.x * 128;

    {   // stage 4 bf16 tiles: 128 rows x 64 d each
        int row = tid >> 1, hd0 = (tid & 1) * 32;
        long qrow = ((long)bh * SS + q0 + row) * HD + hd0;
        long krow = ((long)bh * SS + k0 + row) * HD + hd0;
        unsigned so = (row * PAD + hd0) * 2;
#pragma unroll
        for (int i = 0; i < 4; i++) {
            *(float4*)(dynsm + SC_QH + so + i * 16) = *(const float4*)(g_qh + qrow + i * 8);
            *(float4*)(dynsm + SC_QL + so + i * 16) = *(const float4*)(g_ql + qrow + i * 8);
            *(float4*)(dynsm + SC_KH + so + i * 16) = *(const float4*)(g_kh + krow + i * 8);
            *(float4*)(dynsm + SC_KL + so + i * 16) = *(const float4*)(g_kl + krow + i * 8);
        }
    }
    __syncthreads();

    float acc[2][8][4];
#pragma unroll
    for (int i = 0; i < 2; i++)
#pragma unroll
        for (int j = 0; j < 8; j++)
#pragma unroll
            for (int u = 0; u < 4; u++) acc[i][j][u] = 0.f;

    const int o8 = lane >> 3;
    const unsigned a_off = ((wm * 32 + (lane & 15)) * PAD + (lane >> 4) * 8) * 2;
    const unsigned b_off = ((wn * 64 + (lane & 7) + (o8 >> 1) * 8) * PAD + (o8 & 1) * 8) * 2;

#pragma unroll
    for (int kk = 0; kk < 64; kk += 16) {
        unsigned Ah[2][4], Al[2][4], B[4][4];
        ldsm4(Ah[0], sbase + SC_QH + a_off + kk * 2);
        ldsm4(Ah[1], sbase + SC_QH + a_off + kk * 2 + 16 * ROWB);
        ldsm4(Al[0], sbase + SC_QL + a_off + kk * 2);
        ldsm4(Al[1], sbase + SC_QL + a_off + kk * 2 + 16 * ROWB);
#pragma unroll
        for (int j = 0; j < 4; j++)
            ldsm4(B[j], sbase + SC_KH + b_off + kk * 2 + j * 16 * ROWB);
#pragma unroll
        for (int mi = 0; mi < 2; mi++)
#pragma unroll
            for (int j = 0; j < 4; j++) {
                mmabf(acc[mi][2 * j], Ah[mi], B[j][0], B[j][1]);
                mmabf(acc[mi][2 * j + 1], Ah[mi], B[j][2], B[j][3]);
            }
#pragma unroll
        for (int mi = 0; mi < 2; mi++)
#pragma unroll
            for (int j = 0; j < 4; j++) {
                mmabf(acc[mi][2 * j], Al[mi], B[j][0], B[j][1]);
                mmabf(acc[mi][2 * j + 1], Al[mi], B[j][2], B[j][3]);
            }
#pragma unroll
        for (int j = 0; j < 4; j++)
            ldsm4(B[j], sbase + SC_KL + b_off + kk * 2 + j * 16 * ROWB);
#pragma unroll
        for (int mi = 0; mi < 2; mi++)
#pragma unroll
            for (int j = 0; j < 4; j++) {
                mmabf(acc[mi][2 * j], Ah[mi], B[j][0], B[j][1]);
                mmabf(acc[mi][2 * j + 1], Ah[mi], B[j][2], B[j][3]);
            }
    }

    const int r0 = lane >> 2, cp = (lane & 3) * 2;
#pragma unroll
    for (int mi = 0; mi < 2; mi++)
#pragma unroll
        for (int j = 0; j < 8; j++) {
            int k = k0 + wn * 64 + j * 8 + cp;
#pragma unroll
            for (int half = 0; half < 2; half++) {
                int q = q0 + wm * 32 + mi * 16 + r0 + half * 8;
                float2 o;
                o.x = acc[mi][j][half * 2] * 0.125f;
                o.y = acc[mi][j][half * 2 + 1] * 0.125f;
                *(float2*)(prob + ((long)bh * SS + q) * SS + k) = o;
            }
        }
}

// ---------------------------------------------------------------------------
// Softmax + mask + rel-blend, in place on prob.  [R13 proven]
// 384 threads = 12 warps; phase A rel_attn once, phase B warp-per-head.
// ---------------------------------------------------------------------------
#define SM_WARPS 12

__device__ __forceinline__ float bredMax12(float v, volatile float* red) {
#pragma unroll
    for (int o = 16; o; o >>= 1) v = fmaxf(v, __shfl_xor_sync(0xffffffffu, v, o));
    if ((threadIdx.x & 31) == 0) red[threadIdx.x >> 5] = v;
    __syncthreads();
    float r = red[0];
#pragma unroll
    for (int i = 1; i < SM_WARPS; i++) r = fmaxf(r, red[i]);
    __syncthreads();
    return r;
}
__device__ __forceinline__ float bredSum12(float v, volatile float* red) {
#pragma unroll
    for (int o = 16; o; o >>= 1) v += __shfl_xor_sync(0xffffffffu, v, o);
    if ((threadIdx.x & 31) == 0) red[threadIdx.x >> 5] = v;
    __syncthreads();
    float r = 0.f;
#pragma unroll
    for (int i = 0; i < SM_WARPS; i++) r += red[i];
    __syncthreads();
    return r;
}

__global__ __launch_bounds__(384) void softmax_kernel(
    const float* __restrict__ rel, const void* __restrict__ mask,
    const float* __restrict__ l1p, float* __restrict__ prob)
{
    __shared__ float relp[1024];   // l1 * rel_attn
    __shared__ float msk[1024];
    __shared__ float red[SM_WARPS];

    const int b = blockIdx.y, q = blockIdx.x, tid = threadIdx.x;
    const int mode = g_mask_mode;
    const long mbase = ((long)(b * SS + q)) * SS;

    // ---- Phase A: rel_attn row (head-independent), once ----
    float v[4] = {-3.0e38f, -3.0e38f, -3.0e38f, -3.0e38f};
    float rr[4];
    if (tid < 256) {
        float4 r4 = *(const float4*)(rel + mbase + tid * 4);
        rr[0] = r4.x; rr[1] = r4.y; rr[2] = r4.z; rr[3] = r4.w;
#pragma unroll
        for (int u = 0; u < 4; u++) {
            float mv = maskAt(mask, mbase + tid * 4 + u, mode);
            msk[tid * 4 + u] = mv;
            v[u] = (mv != 0.f) ? rr[u] : -1.0e4f;
        }
    }
    float mx = bredMax12(fmaxf(fmaxf(v[0], v[1]), fmaxf(v[2], v[3])), red);
    float e[4] = {0.f, 0.f, 0.f, 0.f};
    float s = 0.f;
    if (tid < 256) {
#pragma unroll
        for (int u = 0; u < 4; u++) { e[u] = __expf(v[u] - mx); s += e[u]; }
    }
    float tot = bredSum12(s, red);
    const float l1v = *l1p;
    const float w0 = 1.f - l1v;
    float li = l1v / tot;
    if (tid < 256) {
#pragma unroll
        for (int u = 0; u < 4; u++) relp[tid * 4 + u] = e[u] * li;
    }
    __syncthreads();

    // ---- Phase B: one warp per head ----
    const int warp = tid >> 5, lane = tid & 31;
    const int h = warp;
    float* row = prob + (((long)(b * HH + h) * SS) + q) * SS;
    float sv[32];
    float hm = -3.0e38f;
#pragma unroll
    for (int i = 0; i < 8; i++) {
        int idx = i * 128 + lane * 4;
        float4 s4 = *(const float4*)(row + idx);
        float t0 = (msk[idx + 0] != 0.f) ? -1.0e9f : s4.x;
        float t1 = (msk[idx + 1] != 0.f) ? -1.0e9f : s4.y;
        float t2 = (msk[idx + 2] != 0.f) ? -1.0e9f : s4.z;
        float t3 = (msk[idx + 3] != 0.f) ? -1.0e9f : s4.w;
        sv[i * 4 + 0] = t0; sv[i * 4 + 1] = t1;
        sv[i * 4 + 2] = t2; sv[i * 4 + 3] = t3;
        hm = fmaxf(hm, fmaxf(fmaxf(t0, t1), fmaxf(t2, t3)));
    }
#pragma unroll
    for (int o = 16; o; o >>= 1) hm = fmaxf(hm, __shfl_xor_sync(0xffffffffu, hm, o));
    float hs = 0.f;
#pragma unroll
    for (int i = 0; i < 32; i++) {
        sv[i] = __expf(sv[i] - hm);
        hs += sv[i];
    }
#pragma unroll
    for (int o = 16; o; o >>= 1) hs += __shfl_xor_sync(0xffffffffu, hs, o);
    float wi = w0 / hs;
#pragma unroll
    for (int i = 0; i < 8; i++) {
        int idx = i * 128 + lane * 4;
        float4 o4;
        o4.x = sv[i * 4 + 0] * wi + relp[idx + 0];
        o4.y = sv[i * 4 + 1] * wi + relp[idx + 1];
        o4.z = sv[i * 4 + 2] * wi + relp[idx + 2];
        o4.w = sv[i * 4 + 3] * wi + relp[idx + 3];
        *(float4*)(row + idx) = o4;
    }
}

// ---------------------------------------------------------------------------
// PV (HMMA): out[bh,q,d] = sum_s P[q][s] * V[s][d].  [R10 proven]
// ---------------------------------------------------------------------------
#define PV_PH 0
#define PV_PL (PV_PH + 128 * ROWB)
#define PV_VH (PV_PL + 128 * ROWB)
#define PV_VL (PV_VH + 64 * ROWB)
#define PV_SMEM (PV_VL + 64 * ROWB)

__global__ __launch_bounds__(256, 2) void pv_kernel(
    const float* __restrict__ prob, float* __restrict__ out0)
{
    extern __shared__ char dynsm[];
    const unsigned sbase = smem_u32(dynsm);
    const int tid = threadIdx.x;
    const int lane = tid & 31, warp = tid >> 5;
    const int wm = warp & 3, wn = warp >> 2;
    const int bh = blockIdx.y;
    const int q0 = blockIdx.x * 128;
    const int b = bh / HH, h = bh - b * HH;

    float acc[2][4][4];
#pragma unroll
    for (int i = 0; i < 2; i++)
#pragma unroll
        for (int j = 0; j < 4; j++)
#pragma unroll
            for (int u = 0; u < 4; u++) acc[i][j][u] = 0.f;

    const int o8 = lane >> 3;
    const unsigned a_off = ((wm * 32 + (lane & 15)) * PAD + (lane >> 4) * 8) * 2;
    const unsigned bt_row = (lane & 7) + (o8 & 1) * 8;
    const unsigned bt_col = wn * 32 + (o8 >> 1) * 8;

    for (int c = 0; c < 16; c++) {
        __syncthreads();
        {   // stage P chunk: 128 q-rows x 64 s fp32 -> split
            int row = tid >> 1, sh = (tid & 1) * 32;
            const float* g = prob + ((long)bh * SS + q0 + row) * SS + c * 64 + sh;
#pragma unroll
            for (int i = 0; i < 8; i++) {
                float4 v = *(const float4*)(g + i * 4);
                unsigned h0, l0, h1, l1;
                split_pair(v.x, v.y, h0, l0);
                split_pair(v.z, v.w, h1, l1);
                unsigned o = (row * PAD + sh + i * 4) * 2;
                *(uint2*)(dynsm + PV_PH + o) = make_uint2(h0, h1);
                *(uint2*)(dynsm + PV_PL + o) = make_uint2(l0, l1);
            }
        }
        {   // stage V chunk: 64 s-rows x 64 d bf16 (hi/lo)
            int s = tid >> 2, dq = (tid & 3) * 16;
            long idx = ((long)bh * SS + c * 64 + s) * HD + dq;
            unsigned so = (s * PAD + dq) * 2;
            *(float4*)(dynsm + PV_VH + so) = *(const float4*)(g_vh + idx);
            *(float4*)(dynsm + PV_VH + so + 16) = *(const float4*)(g_vh + idx + 8);
            *(float4*)(dynsm + PV_VL + so) = *(const float4*)(g_vl + idx);
            *(float4*)(dynsm + PV_VL + so + 16) = *(const float4*)(g_vl + idx + 8);
        }
        __syncthreads();

#pragma unroll
        for (int kk = 0; kk < 64; kk += 16) {
            unsigned Ah[2][4], Al[2][4], B[2][4];
            ldsm4(Ah[0], sbase + PV_PH + a_off + kk * 2);
            ldsm4(Ah[1], sbase + PV_PH + a_off + kk * 2 + 16 * ROWB);
            ldsm4(Al[0], sbase + PV_PL + a_off + kk * 2);
            ldsm4(Al[1], sbase + PV_PL + a_off + kk * 2 + 16 * ROWB);
            unsigned bo = ((kk + bt_row) * PAD + bt_col) * 2;
            ldsm4t(B[0], sbase + PV_VH + bo);
            ldsm4t(B[1], sbase + PV_VH + bo + 16 * 2);
#pragma unroll
            for (int mi = 0; mi < 2; mi++)
#pragma unroll
                for (int j = 0; j < 2; j++) {
                    mmabf(acc[mi][2 * j], Ah[mi], B[j][0], B[j][1]);
                    mmabf(acc[mi][2 * j + 1], Ah[mi], B[j][2], B[j][3]);
                }
#pragma unroll
            for (int mi = 0; mi < 2; mi++)
#pragma unroll
                for (int j = 0; j < 2; j++) {
                    mmabf(acc[mi][2 * j], Al[mi], B[j][0], B[j][1]);
                    mmabf(acc[mi][2 * j + 1], Al[mi], B[j][2], B[j][3]);
                }
            ldsm4t(B[0], sbase + PV_VL + bo);
            ldsm4t(B[1], sbase + PV_VL + bo + 16 * 2);
#pragma unroll
            for (int mi = 0; mi < 2; mi++)
#pragma unroll
                for (int j = 0; j < 2; j++) {
                    mmabf(acc[mi][2 * j], Ah[mi], B[j][0], B[j][1]);
                    mmabf(acc[mi][2 * j + 1], Ah[mi], B[j][2], B[j][3]);
                }
        }
    }

    const int r0 = lane >> 2, cp = (lane & 3) * 2;
#pragma unroll
    for (int mi = 0; mi < 2; mi++)
#pragma unroll
        for (int j2 = 0; j2 < 4; j2++) {
            int d = wn * 32 + j2 * 8 + cp;
#pragma unroll
            for (int half = 0; half < 2; half++) {
                int q = q0 + wm * 32 + mi * 16 + r0 + half * 8;
                float2 o;
                o.x = acc[mi][j2][half * 2];
                o.y = acc[mi][j2][half * 2 + 1];
                *(float2*)(out0 + ((long)(b * SS) + q) * DD + h * HD + d) = o;
            }
        }
}

// ---------------------------------------------------------------------------
extern "C" void kernel_launch(void* const* d_in, const int* in_sizes, int n_in,
                              void* d_out, int out_size)
{
    const float* query = (const float*)d_in[0];
    const float* key_t = (const float*)d_in[1];
    const float* value = (const float*)d_in[2];
    const float* rel   = (const float*)d_in[3];
    const void*  mask  = d_in[4];
    const float* l1    = (const float*)d_in[5];
    const float* Wq = (const float*)d_in[6];
    const float* bq = (const float*)d_in[7];
    const float* Wk = (const float*)d_in[8];
    const float* bk = (const float*)d_in[9];
    const float* Wv = (const float*)d_in[10];
    const float* bv = (const float*)d_in[11];

    float* out0 = (float*)d_out;                 // (B,S,D)
    float* prob = out0 + (long)BB * SS * DD;     // (B,H,S,S) scores->prob

    cudaFuncSetAttribute(proj_kernel,
                         cudaFuncAttributeMaxDynamicSharedMemorySize, PJ_SMEM);
    cudaFuncSetAttribute(score_kernel,
                         cudaFuncAttributeMaxDynamicSharedMemorySize, SC_SMEM);
    cudaFuncSetAttribute(pv_kernel,
                         cudaFuncAttributeMaxDynamicSharedMemorySize, PV_SMEM);

    detect_mask_kernel<<<1, 256>>>((const unsigned char*)mask);

    // Pre-split inputs and weights into bf16 hi/lo
    __nv_bfloat16 *inh, *inl, *wh, *wl;
    cudaGetSymbolAddress((void**)&inh, g_inh);
    cudaGetSymbolAddress((void**)&inl, g_inl);
    cudaGetSymbolAddress((void**)&wh, g_wh);
    cudaGetSymbolAddress((void**)&wl, g_wl);
    const long XN = (long)MM * DD, WN = (long)DD * DD;
    split_kernel<<<XN / 1024, 256>>>(query, inh, inl);
    split_kernel<<<XN / 1024, 256>>>(key_t, inh + XN, inl + XN);
    split_kernel<<<XN / 1024, 256>>>(value, inh + 2 * XN, inl + 2 * XN);
    split_kernel<<<WN / 1024, 256>>>(Wq, wh, wl);
    split_kernel<<<WN / 1024, 256>>>(Wk, wh + WN, wl + WN);
    split_kernel<<<WN / 1024, 256>>>(Wv, wh + 2 * WN, wl + 2 * WN);

    dim3 pgrid(DD / 128, MM / 128, 3);
    proj_kernel<<<pgrid, 256, PJ_SMEM>>>(bq, bk, bv);

    dim3 sgrid(SS / 128, SS / 128, NBH);
    score_kernel<<<sgrid, 256, SC_SMEM>>>(prob);

    dim3 smgrid(SS, BB);
    softmax_kernel<<<smgrid, 384>>>(rel, mask, l1, prob);

    dim3 vgrid(SS / 128, NBH);
    pv_kernel<<<vgrid, 256, PV_SMEM>>>(prob, out0);
}